// round 12
// baseline (speedup 1.0000x reference)
#include <cuda_runtime.h>
#include <cuda_bf16.h>

#define N_PRED   1024
#define M_GT     2048
#define P        20
#define THREADS  256
#define CHUNKS   (M_GT / THREADS)   // 8 chunks of 256 gt rows
#define WARPS    (THREADS / 32)     // 8
#define ROW_PAD  44                 // floats per padded smem row (176 B):
                                    // stride 44 mod 32 banks -> LDS.128
                                    // phases are conflict-free
#define Q_PER_ROW 10                // float4 quads per gt row (40 floats)

typedef unsigned long long u64;

__device__ __forceinline__ float fsqrt_approx(float x) {
    float r;
    asm("sqrt.approx.f32 %0, %1;" : "=f"(r) : "f"(x));
    return r;
}
__device__ __forceinline__ u64 pack2(float lo, float hi) {
    u64 r;
    asm("mov.b64 %0, {%1, %2};"
        : "=l"(r) : "r"(__float_as_uint(lo)), "r"(__float_as_uint(hi)));
    return r;
}
__device__ __forceinline__ void unpack2(u64 v, float& lo, float& hi) {
    unsigned a, b;
    asm("mov.b64 {%0, %1}, %2;" : "=r"(a), "=r"(b) : "l"(v));
    lo = __uint_as_float(a);
    hi = __uint_as_float(b);
}
__device__ __forceinline__ u64 add2(u64 a, u64 b) {
    u64 r; asm("add.rn.f32x2 %0, %1, %2;" : "=l"(r) : "l"(a), "l"(b)); return r;
}
__device__ __forceinline__ u64 mul2(u64 a, u64 b) {
    u64 r; asm("mul.rn.f32x2 %0, %1, %2;" : "=l"(r) : "l"(a), "l"(b)); return r;
}
__device__ __forceinline__ u64 fma2(u64 a, u64 b, u64 c) {
    u64 r; asm("fma.rn.f32x2 %0, %1, %2, %3;" : "=l"(r) : "l"(a), "l"(b), "l"(c)); return r;
}
// Magic inverse-sqrt seed (ALU pipe: shift+sub per lane).
__device__ __forceinline__ float rsqrt_seed(float x) {
    unsigned i = __float_as_uint(x);
    i = 0x5f3759dfu - (i >> 1);
    return __uint_as_float(i);
}

__global__ __launch_bounds__(THREADS)
void PointMatcher_29437705847326_kernel(const float* __restrict__ pred,
                                        const float* __restrict__ gt,
                                        float* __restrict__ out_points,
                                        float* __restrict__ out_conf,
                                        float* __restrict__ out_idx) {
    const int n   = blockIdx.x;
    const int tid = threadIdx.x;

    // gt staging buffer: 256 rows x 44 floats (last 4 are padding). 45 KB.
    __shared__ __align__(16) float s_gt[THREADS * ROW_PAD];
    __shared__ __align__(16) u64 s_np[10][2];
    __shared__ float s_wmin[WARPS];
    __shared__ int   s_widx[WARPS];
    __shared__ int   s_best;

    if (tid < 10) {
        const float4 pv = reinterpret_cast<const float4*>(pred)[n * 10 + tid];
        s_np[tid][0] = pack2(-pv.x, -pv.z);
        s_np[tid][1] = pack2(-pv.y, -pv.w);
    }

    const u64 c_neg_half = pack2(-0.5f, -0.5f);
    const u64 c_1p5      = pack2(1.5f, 1.5f);

    float best  = 3.4e38f;
    int   bestm = 0;

    const float4* gt4 = reinterpret_cast<const float4*>(gt);

    for (int c = 0; c < CHUNKS; c++) {
        __syncthreads();   // previous compute done (also covers s_np init)

        // Stage 256 gt rows, fully coalesced: 10 consecutive float4s/thread.
        // float4 index f covers row f/10, quad f%10 of this chunk.
#pragma unroll
        for (int k = 0; k < Q_PER_ROW; k++) {
            const int f = k * THREADS + tid;
            const float4 v = gt4[c * (THREADS * Q_PER_ROW) + f];
            const int row = f / Q_PER_ROW;
            const int q   = f % Q_PER_ROW;
            *reinterpret_cast<float4*>(&s_gt[row * ROW_PAD + q * 4]) = v;
        }
        __syncthreads();   // chunk staged

        // Each thread scores its own row (conflict-free LDS.128, stride 44).
        const int m = c * THREADS + tid;   // ascending in c
        const float* rowp = &s_gt[tid * ROW_PAD];
        u64 acc_mufu = 0;
        u64 acc_fma  = 0;
#pragma unroll
        for (int i = 0; i < 10; i++) {
            const float4 g = *reinterpret_cast<const float4*>(rowp + i * 4);
            const u64 gx = pack2(g.x, g.z);
            const u64 gy = pack2(g.y, g.w);
            const u64 dx = add2(gx, s_np[i][0]);   // g - pred (x lanes)
            const u64 dy = add2(gy, s_np[i][1]);   // g - pred (y lanes)
            const u64 s  = fma2(dy, dy, mul2(dx, dx));
            if (i & 1) {
                // FMA-pipe sqrt: magic rsqrt seed + 3 packed Newton iters
                // (rel err ~1e-7, matches MUFU). s == 0 benign.
                float s0, s1;
                unpack2(s, s0, s1);
                u64 r = pack2(rsqrt_seed(s0), rsqrt_seed(s1));
                const u64 nxh = mul2(s, c_neg_half);
                r = mul2(r, fma2(nxh, mul2(r, r), c_1p5));
                r = mul2(r, fma2(nxh, mul2(r, r), c_1p5));
                r = mul2(r, fma2(nxh, mul2(r, r), c_1p5));
                acc_fma = add2(acc_fma, mul2(s, r));
            } else {
                float s0, s1;
                unpack2(s, s0, s1);
                acc_mufu = add2(acc_mufu,
                                pack2(fsqrt_approx(s0), fsqrt_approx(s1)));
            }
        }
        const u64 acc2 = add2(acc_mufu, acc_fma);
        float a0, a1;
        unpack2(acc2, a0, a1);
        const float sum = a0 + a1;
        // m ascends within a thread; strict < keeps the first (smallest) m.
        if (sum < best) { best = sum; bestm = m; }
    }

    // Warp min+argmin (smaller-index tie-break), then combine 8 warp partials.
#pragma unroll
    for (int off = 16; off > 0; off >>= 1) {
        const float o  = __shfl_down_sync(0xffffffffu, best, off);
        const int   oi = __shfl_down_sync(0xffffffffu, bestm, off);
        if (o < best || (o == best && oi < bestm)) { best = o; bestm = oi; }
    }
    if ((tid & 31) == 0) {
        s_wmin[tid >> 5] = best;
        s_widx[tid >> 5] = bestm;
    }
    __syncthreads();

    if (tid == 0) {
        float bm = s_wmin[0];
        int   bi = s_widx[0];
#pragma unroll
        for (int w = 1; w < WARPS; w++) {
            const float v = s_wmin[w];
            const int   vi = s_widx[w];
            if (v < bm || (v == bm && vi < bi)) { bm = v; bi = vi; }
        }
        s_best = bi;
        const float md = bm * (1.0f / (float)P);   // mean distance
        const float conf = (md > 2.0f) ? 0.0f : __expf(-md);
        out_conf[n] = conf;
        out_idx[n]  = (float)bi;
    }
    __syncthreads();

    // Gather matched gt row -> out_points[n]
    if (tid < 10) {
        const float4 gb = reinterpret_cast<const float4*>(gt)[s_best * 10 + tid];
        reinterpret_cast<float4*>(out_points + n * (P * 2))[tid] = gb;
    }
}

extern "C" void kernel_launch(void* const* d_in, const int* in_sizes, int n_in,
                              void* d_out, int out_size) {
    const float* pred = (const float*)d_in[0];   // (1024, 20, 2) f32
    const float* gt   = (const float*)d_in[1];   // (2048, 20, 2) f32
    float* out = (float*)d_out;

    // Output layout (validated R4): points | confidence | indices (as f32).
    float* out_points = out;
    float* out_conf   = out + N_PRED * P * 2;
    float* out_idx    = out + N_PRED * P * 2 + N_PRED;

    PointMatcher_29437705847326_kernel<<<N_PRED, THREADS>>>(
        pred, gt, out_points, out_conf, out_idx);
}

// round 13
// speedup vs baseline: 1.0398x; 1.0398x over previous
#include <cuda_runtime.h>
#include <cuda_bf16.h>

#define N_PRED   1024
#define M_GT     2048
#define P        20
#define THREADS  256
#define M_PER_T  (M_GT / THREADS)   // 8
#define WARPS    (THREADS / 32)     // 8

typedef unsigned long long u64;

__device__ __forceinline__ float fsqrt_approx(float x) {
    float r;
    asm("sqrt.approx.f32 %0, %1;" : "=f"(r) : "f"(x));
    return r;
}
__device__ __forceinline__ u64 pack2(float lo, float hi) {
    u64 r;
    asm("mov.b64 %0, {%1, %2};"
        : "=l"(r) : "r"(__float_as_uint(lo)), "r"(__float_as_uint(hi)));
    return r;
}
__device__ __forceinline__ void unpack2(u64 v, float& lo, float& hi) {
    unsigned a, b;
    asm("mov.b64 {%0, %1}, %2;" : "=r"(a), "=r"(b) : "l"(v));
    lo = __uint_as_float(a);
    hi = __uint_as_float(b);
}
__device__ __forceinline__ u64 add2(u64 a, u64 b) {
    u64 r; asm("add.rn.f32x2 %0, %1, %2;" : "=l"(r) : "l"(a), "l"(b)); return r;
}
__device__ __forceinline__ u64 mul2(u64 a, u64 b) {
    u64 r; asm("mul.rn.f32x2 %0, %1, %2;" : "=l"(r) : "l"(a), "l"(b)); return r;
}

// One point's squared distance + sqrt, 5 warp-instrs, no packing MOVs:
// g and np are (x,y) / (-px,-py) pairs living in aligned register pairs.
__device__ __forceinline__ float point_dist(u64 g, u64 np) {
    const u64 d  = add2(g, np);      // (dx, dy)
    const u64 m2 = mul2(d, d);       // (dx^2, dy^2)
    float lo, hi;
    unpack2(m2, lo, hi);             // register-pair split: free
    return fsqrt_approx(lo + hi);
}

__global__ __launch_bounds__(THREADS)
void PointMatcher_29437705847326_kernel(const float* __restrict__ pred,
                                        const float* __restrict__ gt,
                                        float* __restrict__ out_points,
                                        float* __restrict__ out_conf,
                                        float* __restrict__ out_idx) {
    const int n   = blockIdx.x;
    const int tid = threadIdx.x;

    // Negated pred points as (x,y) u64 pairs, staged via smem so ptxas
    // cannot rematerialize from global inside the loop.
    __shared__ __align__(16) u64 s_np[P];
    __shared__ float s_wmin[WARPS];
    __shared__ int   s_widx[WARPS];
    __shared__ int   s_best;

    if (tid < P) {
        const float2 pv = reinterpret_cast<const float2*>(pred)[n * P + tid];
        s_np[tid] = pack2(-pv.x, -pv.y);
    }
    __syncthreads();

    // Pred into registers (20 u64 = 40 regs).
    u64 np[P];
#pragma unroll
    for (int k = 0; k < P; k++) np[k] = s_np[k];

    float best  = 3.4e38f;
    int   bestm = 0;

#pragma unroll 2
    for (int j = 0; j < M_PER_T; j++) {
        const int m = j * THREADS + tid;           // ascending in j
        const ulonglong2* gr =
            reinterpret_cast<const ulonglong2*>(gt + m * (P * 2));
        float accE = 0.0f, accO = 0.0f;            // dual chains for ILP
#pragma unroll
        for (int q = 0; q < P / 2; q++) {
            const ulonglong2 gg = gr[q];           // two (x,y) points
            accE += point_dist(gg.x, np[2 * q]);
            accO += point_dist(gg.y, np[2 * q + 1]);
        }
        const float sum = accE + accO;
        // m ascends within a thread; strict < keeps the first (smallest) m.
        if (sum < best) { best = sum; bestm = m; }
    }

    // Warp min+argmin (smaller-index tie-break), then combine 8 warp partials.
#pragma unroll
    for (int off = 16; off > 0; off >>= 1) {
        const float o  = __shfl_down_sync(0xffffffffu, best, off);
        const int   oi = __shfl_down_sync(0xffffffffu, bestm, off);
        if (o < best || (o == best && oi < bestm)) { best = o; bestm = oi; }
    }
    if ((tid & 31) == 0) {
        s_wmin[tid >> 5] = best;
        s_widx[tid >> 5] = bestm;
    }
    __syncthreads();

    if (tid == 0) {
        float bm = s_wmin[0];
        int   bi = s_widx[0];
#pragma unroll
        for (int w = 1; w < WARPS; w++) {
            const float v = s_wmin[w];
            const int   vi = s_widx[w];
            if (v < bm || (v == bm && vi < bi)) { bm = v; bi = vi; }
        }
        s_best = bi;
        const float md = bm * (1.0f / (float)P);   // mean distance
        const float conf = (md > 2.0f) ? 0.0f : __expf(-md);
        out_conf[n] = conf;
        out_idx[n]  = (float)bi;
    }
    __syncthreads();

    // Gather matched gt row -> out_points[n]
    if (tid < 10) {
        const float4 gb = reinterpret_cast<const float4*>(gt)[s_best * 10 + tid];
        reinterpret_cast<float4*>(out_points + n * (P * 2))[tid] = gb;
    }
}

extern "C" void kernel_launch(void* const* d_in, const int* in_sizes, int n_in,
                              void* d_out, int out_size) {
    const float* pred = (const float*)d_in[0];   // (1024, 20, 2) f32
    const float* gt   = (const float*)d_in[1];   // (2048, 20, 2) f32
    float* out = (float*)d_out;

    // Output layout (validated R4): points | confidence | indices (as f32).
    float* out_points = out;
    float* out_conf   = out + N_PRED * P * 2;
    float* out_idx    = out + N_PRED * P * 2 + N_PRED;

    PointMatcher_29437705847326_kernel<<<N_PRED, THREADS>>>(
        pred, gt, out_points, out_conf, out_idx);
}